// round 1
// baseline (speedup 1.0000x reference)
#include <cuda_runtime.h>
#include <cuda_bf16.h>

// WaveletTransformLayer: x (B=128, T=2048, F=32) fp32
// windows [2,4,8]; output per (b,f): [detail1 (2047) | detail2 (2044) | detail3 (2037) | approx3 (2037)]
// all divided by T. out shape (B, F*8165).
//
// Everything reduces to FIR filters over the raw series s[t] = x[b,t,f]:
//   detail1[i] = (s[i+1]-s[i]) / 2 / T
//   detail2[j] = (-s[j] -2s[j+1] -2s[j+2] +2s[j+3] +3s[j+4]) / 8 / T
//   ma3[m]    = (s0 +3s1 +5s2 +7s3 +8(s4+s5+s6+s7) +7s8 +5s9 +3s10 +s11)/64 / T   (taps at m+k)
//   ma2[m+7]  = (s7 + 2(s8+s9+s10) + s11)/8 / T
//   detail3[m] = ma2[m+7] - ma3[m];  approx3[m] = ma3[m]
// All four outputs at position t need only taps s[t .. t+11].

#define T_FULL 2048
#define F_DIM  32
#define TILE   256
#define HALO   12
#define SPITCH 269          // 268 needed, padded to odd -> conflict-free smem
#define NOUT   8165         // 2047 + 2044 + 2037 + 2037
#define OFF_D2 2047
#define OFF_D3 4091
#define OFF_A3 6128
#define LEN_D1 2047
#define LEN_D2 2044
#define LEN_A3 2037

#define NTHREADS 256

__global__ __launch_bounds__(NTHREADS)
void wavelet_fir_kernel(const float* __restrict__ x, float* __restrict__ out) {
    __shared__ float s[F_DIM * SPITCH];

    const int tile = blockIdx.x;
    const int b    = blockIdx.y;
    const int t0   = tile * TILE;
    const int tid  = threadIdx.x;

    const float* __restrict__ xb = x + (size_t)b * (T_FULL * F_DIM);

    // ---- Load tile + halo, transposing (t,f) -> smem[f][t]. Coalesced:
    // consecutive tid -> consecutive f at the same t (contiguous 128B in gmem).
    #pragma unroll
    for (int idx = tid; idx < (TILE + HALO) * F_DIM; idx += NTHREADS) {
        const int t  = idx >> 5;          // /32
        const int f  = idx & 31;
        const int tg = t0 + t;
        float v = 0.0f;
        if (tg < T_FULL) v = xb[tg * F_DIM + f];
        s[f * SPITCH + t] = v;
    }
    __syncthreads();

    const float C1 = 1.0f / 4096.0f;     // 1/(2*T)
    const float C2 = 1.0f / 16384.0f;    // 1/(8*T)
    const float C3 = 1.0f / 131072.0f;   // 1/(64*T)

    float* __restrict__ ob = out + (size_t)b * (F_DIM * NOUT);

    // ---- Compute: i enumerates (f, pos). Consecutive tid -> consecutive pos
    // within one f -> every STG row-coalesced. Lane-stride-1 LDS: conflict-free.
    #pragma unroll
    for (int i = tid; i < F_DIM * TILE; i += NTHREADS) {
        const int f   = i >> 8;           // TILE = 256
        const int pos = i & (TILE - 1);
        const int tg  = t0 + pos;

        const float* __restrict__ sp = s + f * SPITCH + pos;
        const float v0 = sp[0],  v1 = sp[1],  v2 = sp[2],  v3 = sp[3];
        const float v4 = sp[4],  v5 = sp[5],  v6 = sp[6],  v7 = sp[7];
        const float v8 = sp[8],  v9 = sp[9],  v10 = sp[10], v11 = sp[11];

        float* __restrict__ row = ob + f * NOUT;

        if (tg < LEN_D1)
            row[tg] = (v1 - v0) * C1;

        if (tg < LEN_D2)
            row[OFF_D2 + tg] = (3.0f*v4 + 2.0f*v3 - 2.0f*v2 - 2.0f*v1 - v0) * C2;

        if (tg < LEN_A3) {
            const float ma3 = (v0 + 3.0f*v1 + 5.0f*v2 + 7.0f*v3
                               + 8.0f*(v4 + v5 + v6 + v7)
                               + 7.0f*v8 + 5.0f*v9 + 3.0f*v10 + v11) * C3;
            const float ma2_7 = (v7 + 2.0f*(v8 + v9 + v10) + v11) * C2;
            row[OFF_D3 + tg] = ma2_7 - ma3;
            row[OFF_A3 + tg] = ma3;
        }
    }
}

extern "C" void kernel_launch(void* const* d_in, const int* in_sizes, int n_in,
                              void* d_out, int out_size) {
    const float* x = (const float*)d_in[0];
    float* out = (float*)d_out;
    dim3 grid(T_FULL / TILE, 128);   // 8 tiles x 128 batches
    wavelet_fir_kernel<<<grid, NTHREADS>>>(x, out);
}